// round 9
// baseline (speedup 1.0000x reference)
#include <cuda_runtime.h>
#include <cuda_bf16.h>
#include <mma.h>
#include <math.h>
#include <stdint.h>

using namespace nvcuda;

#define BATCH   4096
#define DDIM    1024
#define NKB     65536
#define NSPLIT  4
#define KBSPLIT (NKB / NSPLIT)      // 16384
#define TOPK    32
#define OUTW    3072
#define TILE_N  256
#define TILES   (KBSPLIT / TILE_N)  // 64 tiles per CTA
#define KCHUNK  64                  // K elems per pipeline stage
#define SPT     (DDIM / KCHUNK)     // 16 chunks per tile
#define NCHUNK  (TILES * SPT)       // 1024
#define NLIST   (NSPLIT * 4)        // 16 partial top-k lists per query
#define NCAND   (NLIST * TOPK)      // 512 candidates per query
#define RESCORE 64                  // exact-rescore margin

// ---- K3 shared memory layout (bytes) ----
// stage: A 128 x 72 bf16 (18432 B) + B 256 x 72 bf16 (36864 B) = 55296 B
#define STG_BYTES 55296
#define OFF_D     110592            // Ds 128x132 fp32 (67584 B), reused per 128-col phase
#define OFF_KQ    178176            // 256 kb_sq (1024 B)
#define K3_SMEM   179200

// ---------------- scratch (static device globals) ----------------
__device__ float          g_q[BATCH * DDIM];     // exact fp32 q (for rescoring)
__device__ __nv_bfloat16  g_qh[BATCH * DDIM];    // bf16 q (for MMA)
__device__ __nv_bfloat16  g_kbh[NKB * DDIM];     // bf16 kb (for MMA)
__device__ float          g_kbsq[NKB];
__device__ float          g_pd[BATCH * NCAND];
__device__ int            g_pi[BATCH * NCAND];

__device__ __forceinline__ float f_inf() { return __int_as_float(0x7f800000); }

__device__ __forceinline__ uint32_t smem_u32(const void* p) {
    uint32_t a;
    asm("{ .reg .u64 t; cvta.to.shared.u64 t, %1; cvt.u32.u64 %0, t; }" : "=r"(a) : "l"(p));
    return a;
}
__device__ __forceinline__ void cp16(uint32_t dst, const void* src) {
    asm volatile("cp.async.cg.shared.global [%0], [%1], 16;" :: "r"(dst), "l"(src));
}
#define CP_COMMIT() asm volatile("cp.async.commit_group;" ::: "memory")
#define CP_WAIT0()  asm volatile("cp.async.wait_group 0;"  ::: "memory")

__device__ __forceinline__ uint2 f4_to_bf8(float4 v) {
    __nv_bfloat162 lo = __floats2bfloat162_rn(v.x, v.y);
    __nv_bfloat162 hi = __floats2bfloat162_rn(v.z, v.w);
    uint2 r;
    r.x = *reinterpret_cast<uint32_t*>(&lo);
    r.y = *reinterpret_cast<uint32_t*>(&hi);
    return r;
}

// ---------------- K1: q = C @ Q^T, exact fp32 SIMT; also emits bf16 q -------
__global__ __launch_bounds__(256) void qgemm_fp32(const float* __restrict__ Cm,
                                                  const float* __restrict__ Qw) {
    __shared__ float At[8][132];
    __shared__ float Bt[8][132];
    const int tid = threadIdx.x;
    const int mbase = blockIdx.y * 128, nbase = blockIdx.x * 128;
    const int tr = tid >> 4, tc = tid & 15;
    const int lr = tid >> 1, lc = (tid & 1) * 4;

    float acc[8][8];
#pragma unroll
    for (int i = 0; i < 8; i++)
#pragma unroll
        for (int j = 0; j < 8; j++) acc[i][j] = 0.f;

    for (int kk = 0; kk < DDIM; kk += 8) {
        float4 av = *reinterpret_cast<const float4*>(Cm + (size_t)(mbase + lr) * DDIM + kk + lc);
        float4 bv = *reinterpret_cast<const float4*>(Qw + (size_t)(nbase + lr) * DDIM + kk + lc);
        __syncthreads();
        At[lc + 0][lr] = av.x; At[lc + 1][lr] = av.y; At[lc + 2][lr] = av.z; At[lc + 3][lr] = av.w;
        Bt[lc + 0][lr] = bv.x; Bt[lc + 1][lr] = bv.y; Bt[lc + 2][lr] = bv.z; Bt[lc + 3][lr] = bv.w;
        __syncthreads();
#pragma unroll
        for (int k = 0; k < 8; k++) {
            float4 a0 = *reinterpret_cast<float4*>(&At[k][tr * 8]);
            float4 a1 = *reinterpret_cast<float4*>(&At[k][tr * 8 + 4]);
            float4 b0 = *reinterpret_cast<float4*>(&Bt[k][tc * 8]);
            float4 b1 = *reinterpret_cast<float4*>(&Bt[k][tc * 8 + 4]);
            float a[8] = {a0.x, a0.y, a0.z, a0.w, a1.x, a1.y, a1.z, a1.w};
            float b[8] = {b0.x, b0.y, b0.z, b0.w, b1.x, b1.y, b1.z, b1.w};
#pragma unroll
            for (int i = 0; i < 8; i++)
#pragma unroll
                for (int j = 0; j < 8; j++) acc[i][j] += a[i] * b[j];
        }
    }
#pragma unroll
    for (int i = 0; i < 8; i++) {
        const size_t rowoff = (size_t)(mbase + tr * 8 + i) * DDIM + nbase + tc * 8;
#pragma unroll
        for (int j = 0; j < 8; j += 4) {
            float4 v = make_float4(acc[i][j], acc[i][j + 1], acc[i][j + 2], acc[i][j + 3]);
            *reinterpret_cast<float4*>(g_q + rowoff + j) = v;
            *reinterpret_cast<uint2*>(g_qh + rowoff + j) = f4_to_bf8(v);
        }
    }
}

// ---------------- K2: kb -> bf16 + row sums of squares (fused) --------------
__global__ __launch_bounds__(256) void kbprep_kernel(const float* __restrict__ kb) {
    int warp = threadIdx.x >> 5, lane = threadIdx.x & 31;
    int row = blockIdx.x * 8 + warp;
    if (row >= NKB) return;
    const float4* p = reinterpret_cast<const float4*>(kb + (size_t)row * DDIM);
    __nv_bfloat16* dst = g_kbh + (size_t)row * DDIM;
    float s = 0.f;
#pragma unroll
    for (int i = 0; i < 8; i++) {
        float4 v = p[lane + i * 32];
        s += v.x * v.x + v.y * v.y + v.z * v.z + v.w * v.w;
        *reinterpret_cast<uint2*>(dst + (lane + i * 32) * 4) = f4_to_bf8(v);
    }
#pragma unroll
    for (int o = 16; o; o >>= 1) s += __shfl_xor_sync(0xffffffffu, s, o);
    if (lane == 0) g_kbsq[row] = s;
}

// ---------------- K3: 512-thread pipelined bf16 MMA + streaming top-32 ------
__device__ __forceinline__ void k3_issue(uint32_t sb, int tid, int mbase, int split, int g) {
    const int t = g >> 4, s = g & 15, stage = g & 1;
    const int kk = s * KCHUNK;
    const int nbase = split * KBSPLIT + t * TILE_N;
    const uint32_t sA = sb + stage * STG_BYTES;
    const uint32_t sB = sA + 18432;
    // A: 128 rows x 64 bf16 (128 B data in 144 B padded rows): 1024 x 16B
#pragma unroll
    for (int i = 0; i < 2; i++) {
        int e = tid + i * 512, r = e >> 3, c = e & 7;
        cp16(sA + (uint32_t)(r * 144 + c * 16),
             g_qh + (size_t)(mbase + r) * DDIM + kk + c * 8);
    }
    // B: 256 rows: 2048 x 16B
#pragma unroll
    for (int i = 0; i < 4; i++) {
        int e = tid + i * 512, r = e >> 3, c = e & 7;
        cp16(sB + (uint32_t)(r * 144 + c * 16),
             g_kbh + (size_t)(nbase + r) * DDIM + kk + c * 8);
    }
    CP_COMMIT();
}

__global__ __launch_bounds__(512, 1) void dist_topk_cp() {
    extern __shared__ char smem[];
    const uint32_t sb = smem_u32(smem);
    float* Ds     = reinterpret_cast<float*>(smem + OFF_D);
    float* s_kbsq = reinterpret_cast<float*>(smem + OFF_KQ);
    const int tid  = threadIdx.x;
    const int warp = tid >> 5, wm = warp >> 2, wn = warp & 3;
    const int mbase = blockIdx.x * 128;
    const int split = blockIdx.y;
    const int row = tid & 127, seg = tid >> 7;       // 4 threads per query row

    float td[TOPK];
    int   ti[TOPK];
#pragma unroll
    for (int k = 0; k < TOPK; k++) { td[k] = f_inf(); ti[k] = 0; }
    float rmax = f_inf();
    int   rpos = 0;

    wmma::fragment<wmma::accumulator, 16, 16, 16, float> fc[2][4];
#pragma unroll
    for (int i = 0; i < 2; i++)
#pragma unroll
        for (int j = 0; j < 4; j++) wmma::fill_fragment(fc[i][j], 0.0f);

    k3_issue(sb, tid, mbase, split, 0);

    for (int g = 0; g < NCHUNK; g++) {
        if ((g & (SPT - 1)) == 0 && tid < 256) {
            const int nbase = split * KBSPLIT + (g >> 4) * TILE_N;
            s_kbsq[tid] = g_kbsq[nbase + tid];
        }
        CP_WAIT0();
        __syncthreads();
        if (g + 1 < NCHUNK) k3_issue(sb, tid, mbase, split, g + 1);

        {
            const __nv_bfloat16* As =
                reinterpret_cast<const __nv_bfloat16*>(smem + (g & 1) * STG_BYTES);
            const __nv_bfloat16* Bs = As + 9216;   // +18432 bytes (128 rows * 144 B)
#pragma unroll
            for (int ks = 0; ks < 4; ks++) {
                wmma::fragment<wmma::matrix_a, 16, 16, 16, __nv_bfloat16, wmma::row_major> fa0, fa1;
                wmma::load_matrix_sync(fa0, As + (wm * 32) * 72 + ks * 16, 72);
                wmma::load_matrix_sync(fa1, As + (wm * 32 + 16) * 72 + ks * 16, 72);
#pragma unroll
                for (int j = 0; j < 4; j++) {
                    wmma::fragment<wmma::matrix_b, 16, 16, 16, __nv_bfloat16, wmma::col_major> fb;
                    wmma::load_matrix_sync(fb, Bs + (wn * 64 + j * 16) * 72 + ks * 16, 72);
                    wmma::mma_sync(fc[0][j], fa0, fb, fc[0][j]);
                    wmma::mma_sync(fc[1][j], fa1, fb, fc[1][j]);
                }
            }
        }

        if ((g & (SPT - 1)) == SPT - 1) {
            const int t = g >> 4;
            const int nbase = split * KBSPLIT + t * TILE_N;
            // two 128-col epilogue phases through one Ds buffer
#pragma unroll 1
            for (int p = 0; p < 2; p++) {
                if ((wn >> 1) == p) {
#pragma unroll
                    for (int i = 0; i < 2; i++)
#pragma unroll
                        for (int j = 0; j < 4; j++)
                            wmma::store_matrix_sync(
                                Ds + (wm * 32 + i * 16) * 132 + (wn & 1) * 64 + j * 16,
                                fc[i][j], 132, wmma::mem_row_major);
                }
                __syncthreads();

                const float* drow = Ds + row * 132 + seg * 32;
                const float* kq   = s_kbsq + p * 128 + seg * 32;
                const int ibase   = nbase + p * 128 + seg * 32;
#pragma unroll 4
                for (int j = 0; j < 32; j++) {
                    float sc = kq[j] - 2.0f * drow[j];
                    if (sc < rmax) {
                        int idx = ibase + j;
#pragma unroll
                        for (int k = 0; k < TOPK; k++)
                            if (k == rpos) { td[k] = sc; ti[k] = idx; }
                        float nm = -3.4e38f;
                        int np = 0;
#pragma unroll
                        for (int k = 0; k < TOPK; k++)
                            if (td[k] > nm) { nm = td[k]; np = k; }
                        rmax = nm; rpos = np;
                    }
                }
                __syncthreads();
            }
#pragma unroll
            for (int i = 0; i < 2; i++)
#pragma unroll
                for (int j = 0; j < 4; j++) wmma::fill_fragment(fc[i][j], 0.0f);
        }
    }

    const int list = split * 4 + seg;
#pragma unroll
    for (int k = 0; k < TOPK; k++) {
        size_t o = ((size_t)(mbase + row) * NLIST + list) * TOPK + k;
        g_pd[o] = td[k];
        g_pi[o] = ti[k];
    }
}

// ---------------- K4: approx top-64 of 512 -> exact rescoring -> top-32 -----
__device__ __forceinline__ float silu_f(float x) { return x / (1.0f + expf(-x)); }

__global__ __launch_bounds__(256) void finalize_kernel(const float* __restrict__ kb,
                                                       const float* __restrict__ Cm,
                                                       const float* __restrict__ Km,
                                                       const float* __restrict__ temp_p,
                                                       float* __restrict__ out) {
    __shared__ float qrow[DDIM];
    __shared__ float cd[NCAND];
    __shared__ int   ci[NCAND];
    __shared__ int   slot64[RESCORE];
    __shared__ float ed[RESCORE];
    __shared__ int   ei[RESCORE];
    __shared__ float sd[TOPK];
    __shared__ int   si[TOPK];
    __shared__ float wts[TOPK];

    const int q = blockIdx.x, tid = threadIdx.x, wid = tid >> 5, lane = tid & 31;

    cd[tid]       = g_pd[(size_t)q * NCAND + tid];
    cd[tid + 256] = g_pd[(size_t)q * NCAND + tid + 256];
    ci[tid]       = g_pi[(size_t)q * NCAND + tid];
    ci[tid + 256] = g_pi[(size_t)q * NCAND + tid + 256];
    reinterpret_cast<float4*>(qrow)[tid] =
        reinterpret_cast<const float4*>(g_q + (size_t)q * DDIM)[tid];
    __syncthreads();

    // rank each candidate among the 512 approx scores (index tiebreak)
#pragma unroll
    for (int h = 0; h < 2; h++) {
        const int me = tid + h * 256;
        float mine = cd[me];
        int r = 0;
#pragma unroll 8
        for (int j = 0; j < NCAND; j++) {
            float v = cd[j];
            r += (v < mine) || (v == mine && j < me);
        }
        if (r < RESCORE) slot64[r] = me;
    }
    __syncthreads();

    // exact fp32 d2 for the top-64 approx candidates (warp w: 8 rows)
#pragma unroll 1
    for (int r8 = 0; r8 < RESCORE / 8; r8++) {
        const int k = wid * (RESCORE / 8) + r8;
        const int kbrow = ci[slot64[k]];
        const float4* rp = reinterpret_cast<const float4*>(kb + (size_t)kbrow * DDIM);
        float acc = 0.f;
#pragma unroll
        for (int c = 0; c < 8; c++) {
            float4 v  = rp[lane + 32 * c];
            float4 qq = reinterpret_cast<float4*>(qrow)[lane + 32 * c];
            float dx = v.x - qq.x, dy = v.y - qq.y, dz = v.z - qq.z, dw = v.w - qq.w;
            acc += dx * dx + dy * dy + dz * dz + dw * dw;
        }
#pragma unroll
        for (int o = 16; o; o >>= 1) acc += __shfl_xor_sync(0xffffffffu, acc, o);
        if (lane == 0) { ed[k] = acc; ei[k] = kbrow; }
    }
    __syncthreads();

    // exact top-32 of the 64 rescored candidates
    if (tid < RESCORE) {
        float mine = ed[tid];
        int r = 0;
#pragma unroll 8
        for (int j = 0; j < RESCORE; j++) {
            float v = ed[j];
            r += (v < mine) || (v == mine && j < tid);
        }
        if (r < TOPK) { sd[r] = mine; si[r] = ei[tid]; }
    }
    __syncthreads();

    // softmax(-sqrt(d2)/temp) over exact distances
    if (wid == 0) {
        float dist  = sqrtf(fmaxf(sd[lane], 0.0f));
        float logit = -dist / temp_p[0];
        float m = logit;
#pragma unroll
        for (int o = 16; o; o >>= 1) m = fmaxf(m, __shfl_xor_sync(0xffffffffu, m, o));
        float e = expf(logit - m);
        float ss = e;
#pragma unroll
        for (int o = 16; o; o >>= 1) ss += __shfl_xor_sync(0xffffffffu, ss, o);
        wts[lane] = e / ss;
    }
    __syncthreads();

    // T = sum_k w_k * kb[idx_k] (rows are L2-hot from rescoring pass)
    float4 acc = make_float4(0.f, 0.f, 0.f, 0.f);
#pragma unroll 4
    for (int k = 0; k < TOPK; k++) {
        float wk = wts[k];
        float4 v = reinterpret_cast<const float4*>(kb + (size_t)si[k] * DDIM)[tid];
        acc.x += wk * v.x; acc.y += wk * v.y; acc.z += wk * v.z; acc.w += wk * v.w;
    }

    float4* o4 = reinterpret_cast<float4*>(out + (size_t)q * OUTW);
    float4 cv = reinterpret_cast<const float4*>(Cm + (size_t)q * DDIM)[tid];
    float4 kv = reinterpret_cast<const float4*>(Km + (size_t)q * DDIM)[tid];
    float4 rr;
    rr.x = silu_f(cv.x); rr.y = silu_f(cv.y); rr.z = silu_f(cv.z); rr.w = silu_f(cv.w);
    o4[tid] = rr;
    rr.x = silu_f(0.5f * kv.x); rr.y = silu_f(0.5f * kv.y);
    rr.z = silu_f(0.5f * kv.z); rr.w = silu_f(0.5f * kv.w);
    o4[256 + tid] = rr;
    rr.x = silu_f(0.25f * acc.x); rr.y = silu_f(0.25f * acc.y);
    rr.z = silu_f(0.25f * acc.z); rr.w = silu_f(0.25f * acc.w);
    o4[512 + tid] = rr;
}

// ---------------- launch ------------------------------------------------------
extern "C" void kernel_launch(void* const* d_in, const int* in_sizes, int n_in,
                              void* d_out, int out_size) {
    int iC = -1, iK = -1, iKB = -1, iQ = -1, iT = -1;
    for (int i = 0; i < n_in; i++) {
        int s = in_sizes[i];
        if (s == NKB * DDIM)        iKB = i;
        else if (s == DDIM * DDIM)  iQ = i;
        else if (s == BATCH * DDIM) { if (iC < 0) iC = i; else iK = i; }
        else if (s == 1)            { if (iT < 0) iT = i; }
    }
    const float* C    = (const float*)d_in[iC];
    const float* Kin  = (const float*)d_in[iK];
    const float* kb   = (const float*)d_in[iKB];
    const float* Qw   = (const float*)d_in[iQ];
    const float* temp = (const float*)d_in[iT];
    float* out = (float*)d_out;

    cudaFuncSetAttribute(dist_topk_cp, cudaFuncAttributeMaxDynamicSharedMemorySize, K3_SMEM);

    qgemm_fp32<<<dim3(DDIM / 128, BATCH / 128), 256>>>(C, Qw);
    kbprep_kernel<<<NKB / 8, 256>>>(kb);
    dist_topk_cp<<<dim3(BATCH / 128, NSPLIT), 512, K3_SMEM>>>();
    finalize_kernel<<<BATCH, 256>>>(kb, C, Kin, temp, out);
}